// round 5
// baseline (speedup 1.0000x reference)
#include <cuda_runtime.h>
#include <cuda_fp16.h>

#define NN 20000
#define NE 320000
#define NB 25
#define SEG 800
#define FULLMASK 0xffffffffu
#define CSTF 1e-5f

#define FMA2(acc, a, b) asm("fma.rn.f32x2 %0, %1, %2, %0;" : "+l"(acc) : "l"(a), "l"(b))

union U2 { unsigned long long u; float2 f; };

// ---------------- device scratch (static, zero at module load; every call restores zeros) ----
__device__ float  g_Q[NN*64];
__device__ __half g_Kh[NN*64];
__device__ __half g_Vh[NN*64];
__device__ float  g_V[NN*64];
__device__ float  g_hidden[NN*64];
__device__ __half g_M1h[(size_t)NN*512];
__device__ __half g_K1h[NN*64];
__device__ float  g_deginv[NN];
__device__ int    g_cnt[NN];               // zeroed by k_scan1 after read
__device__ int    g_cur[NN];               // zeroed by k_pass1 tail
__device__ int    g_colptr[NN+1];
__device__ int    g_bsum[NB];
__device__ int    g_boff[NB+1];
__device__ int    g_srow[NE];
__device__ float  g_snorm[NE];

// int64-vs-int32 detect: sample 32 odd words; all zero => int64.
__device__ __forceinline__ void detect64(const int* __restrict__ ei, int tid, int* s64){
  if(tid < 32){
    bool z = (ei[2*(tid*9973)+1] == 0);
    unsigned bal = __ballot_sync(FULLMASK, z);
    if(tid==0) *s64 = (bal == FULLMASK) ? 1 : 0;
  }
}

__device__ __forceinline__ int colp(int i){
  return g_colptr[i] + g_boff[i/SEG];
}

// ---------------- histogram of in-degrees ----------------
__global__ void __launch_bounds__(256) k_hist(const int* __restrict__ ei){
  __shared__ int s64;
  int tid = threadIdx.x;
  detect64(ei, tid, &s64);
  __syncthreads();
  int e = blockIdx.x*256 + tid;
  int c = s64 ? ei[2*(NE+e)] : ei[NE+e];
  atomicAdd(&g_cnt[c], 1);
}

// ---------------- per-segment exclusive scan + deginv; zeroes g_cnt ----------------
__global__ void __launch_bounds__(256) k_scan1(){
  __shared__ int s[SEG];
  __shared__ int wtot[8];
  int b = blockIdx.x, tid = threadIdx.x;
  for(int i=tid; i<SEG; i+=256){ s[i] = g_cnt[b*SEG+i]; g_cnt[b*SEG+i] = 0; }
  __syncthreads();
  int c0=0,c1=0,c2=0,c3=0,v=0;
  if(tid < 200){
    c0=s[4*tid]; c1=s[4*tid+1]; c2=s[4*tid+2]; c3=s[4*tid+3];
    v = c0+c1+c2+c3;
  }
  int lane = tid & 31, wid = tid >> 5;
  int x = v;
  #pragma unroll
  for(int off=1; off<32; off<<=1){ int y=__shfl_up_sync(FULLMASK,x,off); if(lane>=off) x+=y; }
  if(lane==31) wtot[wid] = x;
  __syncthreads();
  if(tid < 32){
    int w = (tid < 7) ? wtot[tid] : 0;
    #pragma unroll
    for(int off=1; off<32; off<<=1){ int y=__shfl_up_sync(FULLMASK,w,off); if(tid>=off) w+=y; }
    if(tid < 7) wtot[tid] = w;
    if(tid == 6) g_bsum[b] = w;
  }
  __syncthreads();
  if(tid < 200){
    int pre = x - v + (wid>0 ? wtot[wid-1] : 0);
    int base = b*SEG + 4*tid;
    g_colptr[base+0] = pre;
    g_colptr[base+1] = pre + c0;
    g_colptr[base+2] = pre + c0 + c1;
    g_colptr[base+3] = pre + c0 + c1 + c2;
    g_deginv[base+0] = c0 ? rsqrtf((float)c0) : 0.f;
    g_deginv[base+1] = c1 ? rsqrtf((float)c1) : 0.f;
    g_deginv[base+2] = c2 ? rsqrtf((float)c2) : 0.f;
    g_deginv[base+3] = c3 ? rsqrtf((float)c3) : 0.f;
  }
}

// ---------------- scatter edges into CSR ----------------
__global__ void __launch_bounds__(256) k_scatter(const int* __restrict__ ei){
  __shared__ int s64;
  __shared__ int sboff[NB];
  int tid = threadIdx.x;
  detect64(ei, tid, &s64);
  if(tid >= 32 && tid < 64){
    int t = tid - 32;
    int v = (t < NB) ? g_bsum[t] : 0;
    int x = v;
    #pragma unroll
    for(int off=1; off<32; off<<=1){ int y=__shfl_up_sync(FULLMASK,x,off); if(t>=off) x+=y; }
    if(t < NB) sboff[t] = x - v;
    if(blockIdx.x == 0){
      if(t < NB) g_boff[t] = x - v;
      if(t == 31) g_boff[NB] = NE;
    }
  }
  __syncthreads();
  int e = blockIdx.x*256 + tid;
  int r = s64 ? ei[2*e]        : ei[e];
  int c = s64 ? ei[2*(NE+e)]   : ei[NE+e];
  int pos = g_colptr[c] + sboff[c/SEG] + atomicAdd(&g_cur[c], 1);
  g_srow[pos]  = r;
  g_snorm[pos] = g_deginv[r] * g_deginv[c];
}

// ---------------- merged QKV GEMM, f32x2 packed FMA, fp32 weights ----------------
// dyn smem: xs2 float2[64][64] (x dup), ws2 float2[3][64][32] ((W[i][o],W[i][o+32])), bs2 float2[3][32]
#define SMEMQKV (32768 + 49152 + 768)
__global__ void __launch_bounds__(256) k_gemmQKV(const float* __restrict__ x,
    const float* __restrict__ Wq, const float* __restrict__ bq,
    const float* __restrict__ Wk, const float* __restrict__ bk,
    const float* __restrict__ Wv, const float* __restrict__ bv){
  extern __shared__ __align__(16) char dsm[];
  float2* xs2 = (float2*)dsm;                       // [n*64 + i]
  float2* ws2 = (float2*)(dsm + 32768);             // [m*2048 + i*32 + op]
  float2* bs2 = (float2*)(dsm + 32768 + 49152);     // [m*32 + op]
  int nb = blockIdx.x*64;
  int tid = threadIdx.x;
  for(int idx = tid; idx < 4096; idx += 256){
    int n = idx >> 6, i = idx & 63;
    float xv = (nb+n < NN) ? x[(nb+n)*64 + i] : 0.f;
    xs2[n*64+i] = make_float2(xv, xv);
    int wi = idx >> 6, wo = idx & 63;
    int wop = wo & 31, hi = wo >> 5;
    ((float*)&ws2[0*2048 + wi*32 + wop])[hi] = Wq[idx];
    ((float*)&ws2[1*2048 + wi*32 + wop])[hi] = Wk[idx];
    ((float*)&ws2[2*2048 + wi*32 + wop])[hi] = Wv[idx];
  }
  if(tid < 32){
    bs2[tid]    = make_float2(bq[tid], bq[tid+32]);
    bs2[32+tid] = make_float2(bk[tid], bk[tid+32]);
    bs2[64+tid] = make_float2(bv[tid], bv[tid+32]);
  }
  __syncthreads();

  int op = tid & 31;
  int ng = (tid >> 5) << 3;
  U2 acc[3][8];
  #pragma unroll
  for(int m=0;m<3;m++){
    U2 b0; b0.f = bs2[m*32+op];
    #pragma unroll
    for(int g=0;g<8;g++) acc[m][g] = b0;
  }

  const unsigned long long* xsu = (const unsigned long long*)xs2;
  const unsigned long long* wsu = (const unsigned long long*)ws2;
  #pragma unroll 4
  for(int i=0; i<64; i++){
    unsigned long long w0 = wsu[0*2048 + i*32 + op];
    unsigned long long w1 = wsu[1*2048 + i*32 + op];
    unsigned long long w2 = wsu[2*2048 + i*32 + op];
    #pragma unroll
    for(int g=0;g<8;g++){
      unsigned long long xv = xsu[(ng+g)*64 + i];
      FMA2(acc[0][g].u, xv, w0);
      FMA2(acc[1][g].u, xv, w1);
      FMA2(acc[2][g].u, xv, w2);
    }
  }

  #pragma unroll
  for(int g=0;g<8;g++){
    int n = nb + ng + g;
    if(n < NN){
      float q0 = acc[0][g].f.x, q1 = acc[0][g].f.y;
      q0 = (q0 > 0.f) ? (q0 + 1.f) : __expf(q0);
      q1 = (q1 > 0.f) ? (q1 + 1.f) : __expf(q1);
      g_Q[n*64+op] = q0; g_Q[n*64+op+32] = q1;
      float k0 = acc[1][g].f.x, k1 = acc[1][g].f.y;
      k0 = (k0 > 0.f) ? (k0 + 1.f) : __expf(k0);
      k1 = (k1 > 0.f) ? (k1 + 1.f) : __expf(k1);
      g_Kh[n*64+op] = __float2half_rn(k0); g_Kh[n*64+op+32] = __float2half_rn(k1);
      float v0 = acc[2][g].f.x, v1 = acc[2][g].f.y;
      g_V[n*64+op] = v0; g_V[n*64+op+32] = v1;
      g_Vh[n*64+op] = __float2half_rn(v0); g_Vh[n*64+op+32] = __float2half_rn(v1);
    }
  }
}

// ---------------- output GEMM: hidden @ Wo + bo -> dout, f32x2, fp32 weights ------------
#define SMEMO (32768 + 16384 + 256)
__global__ void __launch_bounds__(256) k_gemmO(const float* __restrict__ Wo,
                                               const float* __restrict__ bo,
                                               float* __restrict__ dout){
  extern __shared__ __align__(16) char dsm[];
  float2* xs2 = (float2*)dsm;
  float2* ws2 = (float2*)(dsm + 32768);
  float2* bs2 = (float2*)(dsm + 32768 + 16384);
  int nb = blockIdx.x*64;
  int tid = threadIdx.x;
  for(int idx = tid; idx < 4096; idx += 256){
    int n = idx >> 6, i = idx & 63;
    float xv = (nb+n < NN) ? g_hidden[(nb+n)*64 + i] : 0.f;
    xs2[n*64+i] = make_float2(xv, xv);
    int wi = idx >> 6, wo = idx & 63;
    ((float*)&ws2[wi*32 + (wo & 31)])[wo >> 5] = Wo[idx];
  }
  if(tid < 32) bs2[tid] = make_float2(bo[tid], bo[tid+32]);
  __syncthreads();

  int op = tid & 31;
  int ng = (tid >> 5) << 3;
  U2 acc[8];
  { U2 b0; b0.f = bs2[op];
    #pragma unroll
    for(int g=0;g<8;g++) acc[g] = b0; }

  const unsigned long long* xsu = (const unsigned long long*)xs2;
  const unsigned long long* wsu = (const unsigned long long*)ws2;
  #pragma unroll 8
  for(int i=0; i<64; i++){
    unsigned long long w0 = wsu[i*32 + op];
    #pragma unroll
    for(int g=0;g<8;g++){
      unsigned long long xv = xsu[(ng+g)*64 + i];
      FMA2(acc[g].u, xv, w0);
    }
  }
  #pragma unroll
  for(int g=0;g<8;g++){
    int n = nb + ng + g;
    if(n < NN){
      dout[n*64+op]    = acc[g].f.x;
      dout[n*64+op+32] = acc[g].f.y;
    }
  }
}

// ---------------- hop 1 ----------------
__global__ void __launch_bounds__(256) k_pass1(const float* __restrict__ hopwise,
                                               const float* __restrict__ headwise){
  __shared__ float sgam[8];
  __shared__ float shop0;
  int tid = threadIdx.x;
  if(tid < 8){
    float mx = -1e30f;
    for(int hh=0; hh<8; hh++) mx = fmaxf(mx, headwise[hh*2]);
    float ss = 0.f;
    for(int hh=0; hh<8; hh++) ss += expf(headwise[hh*2]-mx);
    sgam[tid] = hopwise[1] * expf(headwise[tid*2]-mx) / ss;
  }
  if(tid == 8) shop0 = hopwise[0];
  __syncthreads();

  int n    = (blockIdx.x*256 + tid) >> 5;
  int lane = tid & 31;
  int beg = colp(n), end = colp(n+1);
  float m0[8], m1[8];
  #pragma unroll
  for(int j=0;j<8;j++){ m0[j]=0.f; m1[j]=0.f; }
  float ka0 = 0.f, ka1 = 0.f;

  int row = 0; float nrm = 0.f;
  if(beg < end){ row = g_srow[beg]; nrm = g_snorm[beg]; }
  for(int e=beg; e<end; e++){
    int nrow = 0; float nnrm = 0.f;
    if(e+1 < end){ nrow = g_srow[e+1]; nnrm = g_snorm[e+1]; }
    __half2  kh = *(const __half2*) &g_Kh[row*64 + 2*lane];
    unsigned vu = *(const unsigned*)&g_Vh[row*64 + 2*lane];
    float2 kf = __half22float2(kh);
    float a0 = nrm*kf.x, a1 = nrm*kf.y;
    ka0 += a0; ka1 += a1;
    int base = lane & ~3;
    #pragma unroll
    for(int jj=0; jj<4; jj++){
      unsigned u = __shfl_sync(FULLMASK, vu, base + jj);
      float2 vf = __half22float2(*(__half2*)&u);
      m0[2*jj]   = fmaf(a0, vf.x, m0[2*jj]);
      m0[2*jj+1] = fmaf(a0, vf.y, m0[2*jj+1]);
      m1[2*jj]   = fmaf(a1, vf.x, m1[2*jj]);
      m1[2*jj+1] = fmaf(a1, vf.y, m1[2*jj+1]);
    }
    row = nrow; nrm = nnrm;
  }

  {
    union { uint4 u; __half2 h[4]; } p;
    p.h[0]=__floats2half2_rn(m0[0],m0[1]); p.h[1]=__floats2half2_rn(m0[2],m0[3]);
    p.h[2]=__floats2half2_rn(m0[4],m0[5]); p.h[3]=__floats2half2_rn(m0[6],m0[7]);
    *(uint4*)&g_M1h[(size_t)n*512 + lane*8] = p.u;
    p.h[0]=__floats2half2_rn(m1[0],m1[1]); p.h[1]=__floats2half2_rn(m1[2],m1[3]);
    p.h[2]=__floats2half2_rn(m1[4],m1[5]); p.h[3]=__floats2half2_rn(m1[6],m1[7]);
    *(uint4*)&g_M1h[(size_t)n*512 + 256 + lane*8] = p.u;
  }
  *(__half2*)&g_K1h[n*64 + 2*lane] = __floats2half2_rn(ka0, ka1);

  float2 qv = *(const float2*)&g_Q[n*64 + 2*lane];
  float p[8];
  #pragma unroll
  for(int j=0;j<8;j++) p[j] = qv.x*m0[j] + qv.y*m1[j];
  #pragma unroll
  for(int j=0;j<8;j++){
    p[j] += __shfl_xor_sync(FULLMASK, p[j], 1);
    p[j] += __shfl_xor_sync(FULLMASK, p[j], 2);
  }
  float c = qv.x*ka0 + qv.y*ka1;
  c += __shfl_xor_sync(FULLMASK, c, 1);
  c += __shfl_xor_sync(FULLMASK, c, 2);
  int h = lane >> 2, sub = lane & 3;
  if(sub < 2){
    bool lo = (sub == 0);
    float r0 = lo ? p[0] : p[4];
    float r1 = lo ? p[1] : p[5];
    float r2 = lo ? p[2] : p[6];
    float r3 = lo ? p[3] : p[7];
    float inv = sgam[h] / (c + CSTF);
    float hp0 = shop0;
    const float4 vv = *(const float4*)&g_V[n*64 + h*8 + sub*4];
    float4 hv;
    hv.x = fmaf(vv.x, hp0, inv*r0);
    hv.y = fmaf(vv.y, hp0, inv*r1);
    hv.z = fmaf(vv.z, hp0, inv*r2);
    hv.w = fmaf(vv.w, hp0, inv*r3);
    *(float4*)&g_hidden[n*64 + h*8 + sub*4] = hv;
  }
  if(lane == 0) g_cur[n] = 0;
}

// ---------------- hop 2 ----------------
__global__ void __launch_bounds__(256) k_pass3(const float* __restrict__ hopwise,
                                               const float* __restrict__ headwise){
  __shared__ float sgam[8];
  int tid = threadIdx.x;
  if(tid < 8){
    float mx = -1e30f;
    for(int hh=0; hh<8; hh++) mx = fmaxf(mx, headwise[hh*2+1]);
    float ss = 0.f;
    for(int hh=0; hh<8; hh++) ss += expf(headwise[hh*2+1]-mx);
    sgam[tid] = hopwise[2] * expf(headwise[tid*2+1]-mx) / ss;
  }
  __syncthreads();

  int n    = (blockIdx.x*256 + tid) >> 5;
  int lane = tid & 31;
  int beg = colp(n), end = colp(n+1);
  float m[16];
  #pragma unroll
  for(int t=0;t<16;t++) m[t] = 0.f;
  float ca = 0.f, cb = 0.f;

  int row = 0; float nrm = 0.f;
  if(beg < end){ row = g_srow[beg]; nrm = g_snorm[beg]; }
  for(int e=beg; e<end; e++){
    int nrow = 0; float nnrm = 0.f;
    if(e+1 < end){ nrow = g_srow[e+1]; nnrm = g_snorm[e+1]; }
    const __half* Mr = &g_M1h[(size_t)row*512];
    uint4 a = *(const uint4*)(Mr + lane*8);
    uint4 b = *(const uint4*)(Mr + 256 + lane*8);
    __half2 kv = *(const __half2*)&g_K1h[row*64 + 2*lane];
    float2 f;
    f = __half22float2(*(__half2*)&a.x); m[0]=fmaf(nrm,f.x,m[0]);   m[1]=fmaf(nrm,f.y,m[1]);
    f = __half22float2(*(__half2*)&a.y); m[2]=fmaf(nrm,f.x,m[2]);   m[3]=fmaf(nrm,f.y,m[3]);
    f = __half22float2(*(__half2*)&a.z); m[4]=fmaf(nrm,f.x,m[4]);   m[5]=fmaf(nrm,f.y,m[5]);
    f = __half22float2(*(__half2*)&a.w); m[6]=fmaf(nrm,f.x,m[6]);   m[7]=fmaf(nrm,f.y,m[7]);
    f = __half22float2(*(__half2*)&b.x); m[8]=fmaf(nrm,f.x,m[8]);   m[9]=fmaf(nrm,f.y,m[9]);
    f = __half22float2(*(__half2*)&b.y); m[10]=fmaf(nrm,f.x,m[10]); m[11]=fmaf(nrm,f.y,m[11]);
    f = __half22float2(*(__half2*)&b.z); m[12]=fmaf(nrm,f.x,m[12]); m[13]=fmaf(nrm,f.y,m[13]);
    f = __half22float2(*(__half2*)&b.w); m[14]=fmaf(nrm,f.x,m[14]); m[15]=fmaf(nrm,f.y,m[15]);
    float2 kf = __half22float2(kv);
    ca = fmaf(nrm, kf.x, ca);
    cb = fmaf(nrm, kf.y, cb);
    row = nrow; nrm = nnrm;
  }

  float2 qv = *(const float2*)&g_Q[n*64 + 2*lane];
  float p[8];
  #pragma unroll
  for(int j=0;j<8;j++) p[j] = qv.x*m[j] + qv.y*m[8+j];
  #pragma unroll
  for(int j=0;j<8;j++){
    p[j] += __shfl_xor_sync(FULLMASK, p[j], 1);
    p[j] += __shfl_xor_sync(FULLMASK, p[j], 2);
  }
  float c = qv.x*ca + qv.y*cb;
  c += __shfl_xor_sync(FULLMASK, c, 1);
  c += __shfl_xor_sync(FULLMASK, c, 2);
  int h = lane >> 2, sub = lane & 3;
  if(sub < 2){
    bool lo = (sub == 0);
    float r0 = lo ? p[0] : p[4];
    float r1 = lo ? p[1] : p[5];
    float r2 = lo ? p[2] : p[6];
    float r3 = lo ? p[3] : p[7];
    float inv = sgam[h] / (c + CSTF);
    float4* hp = (float4*)&g_hidden[n*64 + h*8 + sub*4];
    float4 hv = *hp;
    hv.x += inv*r0; hv.y += inv*r1; hv.z += inv*r2; hv.w += inv*r3;
    *hp = hv;
  }
}

// ---------------- launch ----------------
extern "C" void kernel_launch(void* const* d_in, const int* in_sizes, int n_in,
                              void* d_out, int out_size){
  const float* x        = (const float*)d_in[0];
  const int*   ei       = (const int*)  d_in[1];
  const float* Wq       = (const float*)d_in[3];
  const float* bq       = (const float*)d_in[4];
  const float* Wk       = (const float*)d_in[5];
  const float* bk       = (const float*)d_in[6];
  const float* Wv       = (const float*)d_in[7];
  const float* bv       = (const float*)d_in[8];
  const float* Wo       = (const float*)d_in[9];
  const float* bo       = (const float*)d_in[10];
  const float* hopwise  = (const float*)d_in[11];
  const float* headwise = (const float*)d_in[12];
  float* out = (float*)d_out;

  cudaFuncSetAttribute(k_gemmQKV, cudaFuncAttributeMaxDynamicSharedMemorySize, SMEMQKV);
  cudaFuncSetAttribute(k_gemmO,   cudaFuncAttributeMaxDynamicSharedMemorySize, SMEMO);

  k_hist   <<<NE/256, 256>>>(ei);
  k_scan1  <<<NB, 256>>>();
  k_scatter<<<NE/256, 256>>>(ei);
  k_gemmQKV<<<(NN+63)/64, 256, SMEMQKV>>>(x, Wq, bq, Wk, bk, Wv, bv);
  k_pass1  <<<NN/8, 256>>>(hopwise, headwise);
  k_pass3  <<<NN/8, 256>>>(hopwise, headwise);
  k_gemmO  <<<(NN+63)/64, 256, SMEMO>>>(Wo, bo, out);
}

// round 6
// speedup vs baseline: 1.0023x; 1.0023x over previous
#include <cuda_runtime.h>
#include <cuda_fp16.h>

#define NN 20000
#define NE 320000
#define NB 25
#define SEG 800
#define FULLMASK 0xffffffffu
#define CSTF 1e-5f
#define GEMMB 313

#define FMA2(acc, a, b) asm("fma.rn.f32x2 %0, %1, %2, %0;" : "+l"(acc) : "l"(a), "l"(b))
#define PACK2(xx, xv)   asm("mov.b64 %0, {%1, %1};" : "=l"(xx) : "f"(xv))

union U2 { unsigned long long u; float2 f; };

// ---------------- device scratch (static, zero at module load; every call restores zeros) ----
__device__ float  g_Q[NN*64];
__device__ __half g_Kh[NN*64];
__device__ __half g_Vh[NN*64];
__device__ float  g_V[NN*64];
__device__ float  g_hidden[NN*64];
__device__ __half g_M1h[(size_t)NN*512];
__device__ __half g_K1h[NN*64];
__device__ float  g_deginv[NN];
__device__ int    g_cnt[NN];               // zeroed by k_scan1 after read
__device__ int    g_cur[NN];               // zeroed by k_pass1 tail
__device__ int    g_colptr[NN+1];
__device__ int    g_bsum[NB];
__device__ int    g_boff[NB+1];
__device__ int    g_srow[NE];
__device__ float  g_snorm[NE];

// int64-vs-int32 detect: sample 32 odd words; all zero => int64.
__device__ __forceinline__ void detect64(const int* __restrict__ ei, int tid, int* s64){
  if(tid < 32){
    bool z = (ei[2*(tid*9973)+1] == 0);
    unsigned bal = __ballot_sync(FULLMASK, z);
    if(tid==0) *s64 = (bal == FULLMASK) ? 1 : 0;
  }
}

__device__ __forceinline__ int colp(int i){
  return g_colptr[i] + g_boff[i/SEG];
}

// ---------------- merged launch: QKV GEMM (blocks < GEMMB) || degree histogram ----------
// dyn smem (gemm blocks): xs float[64*64]=16KB, ws2 float2[3][64][32]=48KB, bs2 float2[3*32]
#define SMEMQKV (16384 + 49152 + 768)
__global__ void __launch_bounds__(256,3) k_gemmQKV_hist(const int* __restrict__ ei,
    const float* __restrict__ x,
    const float* __restrict__ Wq, const float* __restrict__ bq,
    const float* __restrict__ Wk, const float* __restrict__ bk,
    const float* __restrict__ Wv, const float* __restrict__ bv){
  int tid = threadIdx.x;

  if(blockIdx.x >= GEMMB){
    // -------- histogram part (grid-stride over edges) --------
    __shared__ int s64;
    detect64(ei, tid, &s64);
    __syncthreads();
    int b = blockIdx.x - GEMMB;
    for(int e = b*256 + tid; e < NE; e += GEMMB*256){
      int c = s64 ? ei[2*(NE+e)] : ei[NE+e];
      atomicAdd(&g_cnt[c], 1);
    }
    return;
  }

  // -------- GEMM part --------
  extern __shared__ __align__(16) char dsm[];
  float*  xsf = (float*)dsm;                        // [n*64 + i]
  float2* ws2 = (float2*)(dsm + 16384);             // [m*2048 + i*32 + op]
  float2* bs2 = (float2*)(dsm + 16384 + 49152);     // [m*32 + op]
  int nb = blockIdx.x*64;
  for(int idx = tid; idx < 4096; idx += 256){
    int n = idx >> 6, i = idx & 63;
    xsf[idx] = (nb+n < NN) ? x[(nb+n)*64 + i] : 0.f;
    int wi = idx >> 6, wo = idx & 63;
    int wop = wo & 31, hi = wo >> 5;
    ((float*)&ws2[0*2048 + wi*32 + wop])[hi] = Wq[idx];
    ((float*)&ws2[1*2048 + wi*32 + wop])[hi] = Wk[idx];
    ((float*)&ws2[2*2048 + wi*32 + wop])[hi] = Wv[idx];
  }
  if(tid < 32){
    bs2[tid]    = make_float2(bq[tid], bq[tid+32]);
    bs2[32+tid] = make_float2(bk[tid], bk[tid+32]);
    bs2[64+tid] = make_float2(bv[tid], bv[tid+32]);
  }
  __syncthreads();

  int op = tid & 31;
  int ng = (tid >> 5) << 3;
  U2 acc[3][8];
  #pragma unroll
  for(int m=0;m<3;m++){
    U2 b0; b0.f = bs2[m*32+op];
    #pragma unroll
    for(int g=0;g<8;g++) acc[m][g] = b0;
  }

  const unsigned long long* wsu = (const unsigned long long*)ws2;
  #pragma unroll 4
  for(int i=0; i<64; i++){
    unsigned long long w0 = wsu[0*2048 + i*32 + op];
    unsigned long long w1 = wsu[1*2048 + i*32 + op];
    unsigned long long w2 = wsu[2*2048 + i*32 + op];
    #pragma unroll
    for(int g=0;g<8;g++){
      float xv = xsf[(ng+g)*64 + i];
      unsigned long long xx; PACK2(xx, xv);
      FMA2(acc[0][g].u, xx, w0);
      FMA2(acc[1][g].u, xx, w1);
      FMA2(acc[2][g].u, xx, w2);
    }
  }

  #pragma unroll
  for(int g=0;g<8;g++){
    int n = nb + ng + g;
    if(n < NN){
      float q0 = acc[0][g].f.x, q1 = acc[0][g].f.y;
      q0 = (q0 > 0.f) ? (q0 + 1.f) : __expf(q0);
      q1 = (q1 > 0.f) ? (q1 + 1.f) : __expf(q1);
      g_Q[n*64+op] = q0; g_Q[n*64+op+32] = q1;
      float k0 = acc[1][g].f.x, k1 = acc[1][g].f.y;
      k0 = (k0 > 0.f) ? (k0 + 1.f) : __expf(k0);
      k1 = (k1 > 0.f) ? (k1 + 1.f) : __expf(k1);
      g_Kh[n*64+op] = __float2half_rn(k0); g_Kh[n*64+op+32] = __float2half_rn(k1);
      float v0 = acc[2][g].f.x, v1 = acc[2][g].f.y;
      g_V[n*64+op] = v0; g_V[n*64+op+32] = v1;
      g_Vh[n*64+op] = __float2half_rn(v0); g_Vh[n*64+op+32] = __float2half_rn(v1);
    }
  }
}

// ---------------- per-segment exclusive scan + deginv; zeroes g_cnt ----------------
__global__ void __launch_bounds__(256) k_scan1(){
  __shared__ int s[SEG];
  __shared__ int wtot[8];
  int b = blockIdx.x, tid = threadIdx.x;
  for(int i=tid; i<SEG; i+=256){ s[i] = g_cnt[b*SEG+i]; g_cnt[b*SEG+i] = 0; }
  __syncthreads();
  int c0=0,c1=0,c2=0,c3=0,v=0;
  if(tid < 200){
    c0=s[4*tid]; c1=s[4*tid+1]; c2=s[4*tid+2]; c3=s[4*tid+3];
    v = c0+c1+c2+c3;
  }
  int lane = tid & 31, wid = tid >> 5;
  int x = v;
  #pragma unroll
  for(int off=1; off<32; off<<=1){ int y=__shfl_up_sync(FULLMASK,x,off); if(lane>=off) x+=y; }
  if(lane==31) wtot[wid] = x;
  __syncthreads();
  if(tid < 32){
    int w = (tid < 7) ? wtot[tid] : 0;
    #pragma unroll
    for(int off=1; off<32; off<<=1){ int y=__shfl_up_sync(FULLMASK,w,off); if(tid>=off) w+=y; }
    if(tid < 7) wtot[tid] = w;
    if(tid == 6) g_bsum[b] = w;
  }
  __syncthreads();
  if(tid < 200){
    int pre = x - v + (wid>0 ? wtot[wid-1] : 0);
    int base = b*SEG + 4*tid;
    g_colptr[base+0] = pre;
    g_colptr[base+1] = pre + c0;
    g_colptr[base+2] = pre + c0 + c1;
    g_colptr[base+3] = pre + c0 + c1 + c2;
    g_deginv[base+0] = c0 ? rsqrtf((float)c0) : 0.f;
    g_deginv[base+1] = c1 ? rsqrtf((float)c1) : 0.f;
    g_deginv[base+2] = c2 ? rsqrtf((float)c2) : 0.f;
    g_deginv[base+3] = c3 ? rsqrtf((float)c3) : 0.f;
  }
}

// ---------------- scatter edges into CSR ----------------
__global__ void __launch_bounds__(256) k_scatter(const int* __restrict__ ei){
  __shared__ int s64;
  __shared__ int sboff[NB];
  int tid = threadIdx.x;
  detect64(ei, tid, &s64);
  if(tid >= 32 && tid < 64){
    int t = tid - 32;
    int v = (t < NB) ? g_bsum[t] : 0;
    int x = v;
    #pragma unroll
    for(int off=1; off<32; off<<=1){ int y=__shfl_up_sync(FULLMASK,x,off); if(t>=off) x+=y; }
    if(t < NB) sboff[t] = x - v;
    if(blockIdx.x == 0){
      if(t < NB) g_boff[t] = x - v;
      if(t == 31) g_boff[NB] = NE;
    }
  }
  __syncthreads();
  int e = blockIdx.x*256 + tid;
  int r = s64 ? ei[2*e]        : ei[e];
  int c = s64 ? ei[2*(NE+e)]   : ei[NE+e];
  int pos = g_colptr[c] + sboff[c/SEG] + atomicAdd(&g_cur[c], 1);
  g_srow[pos]  = r;
  g_snorm[pos] = g_deginv[r] * g_deginv[c];
}

// ---------------- output GEMM: hidden @ Wo + bo -> dout ----------------
#define SMEMO (16384 + 16384 + 256)
__global__ void __launch_bounds__(256,4) k_gemmO(const float* __restrict__ Wo,
                                                 const float* __restrict__ bo,
                                                 float* __restrict__ dout){
  extern __shared__ __align__(16) char dsm[];
  float*  xsf = (float*)dsm;
  float2* ws2 = (float2*)(dsm + 16384);
  float2* bs2 = (float2*)(dsm + 16384 + 16384);
  int nb = blockIdx.x*64;
  int tid = threadIdx.x;
  for(int idx = tid; idx < 4096; idx += 256){
    int n = idx >> 6;
    xsf[idx] = (nb+n < NN) ? g_hidden[nb*64 + idx] : 0.f;
    int wi = idx >> 6, wo = idx & 63;
    ((float*)&ws2[wi*32 + (wo & 31)])[wo >> 5] = Wo[idx];
  }
  if(tid < 32) bs2[tid] = make_float2(bo[tid], bo[tid+32]);
  __syncthreads();

  int op = tid & 31;
  int ng = (tid >> 5) << 3;
  U2 acc[8];
  { U2 b0; b0.f = bs2[op];
    #pragma unroll
    for(int g=0;g<8;g++) acc[g] = b0; }

  const unsigned long long* wsu = (const unsigned long long*)ws2;
  #pragma unroll 4
  for(int i=0; i<64; i++){
    unsigned long long w0 = wsu[i*32 + op];
    #pragma unroll
    for(int g=0;g<8;g++){
      float xv = xsf[(ng+g)*64 + i];
      unsigned long long xx; PACK2(xx, xv);
      FMA2(acc[g].u, xx, w0);
    }
  }
  #pragma unroll
  for(int g=0;g<8;g++){
    int n = nb + ng + g;
    if(n < NN){
      dout[n*64+op]    = acc[g].f.x;
      dout[n*64+op+32] = acc[g].f.y;
    }
  }
}

// ---------------- hop 1 ----------------
__global__ void __launch_bounds__(256) k_pass1(const float* __restrict__ hopwise,
                                               const float* __restrict__ headwise){
  __shared__ float sgam[8];
  __shared__ float shop0;
  int tid = threadIdx.x;
  if(tid < 8){
    float mx = -1e30f;
    for(int hh=0; hh<8; hh++) mx = fmaxf(mx, headwise[hh*2]);
    float ss = 0.f;
    for(int hh=0; hh<8; hh++) ss += expf(headwise[hh*2]-mx);
    sgam[tid] = hopwise[1] * expf(headwise[tid*2]-mx) / ss;
  }
  if(tid == 8) shop0 = hopwise[0];
  __syncthreads();

  int n    = (blockIdx.x*256 + tid) >> 5;
  int lane = tid & 31;
  int beg = colp(n), end = colp(n+1);
  float m0[8], m1[8];
  #pragma unroll
  for(int j=0;j<8;j++){ m0[j]=0.f; m1[j]=0.f; }
  float ka0 = 0.f, ka1 = 0.f;

  int row = 0; float nrm = 0.f;
  if(beg < end){ row = g_srow[beg]; nrm = g_snorm[beg]; }
  for(int e=beg; e<end; e++){
    int nrow = 0; float nnrm = 0.f;
    if(e+1 < end){ nrow = g_srow[e+1]; nnrm = g_snorm[e+1]; }
    __half2  kh = *(const __half2*) &g_Kh[row*64 + 2*lane];
    unsigned vu = *(const unsigned*)&g_Vh[row*64 + 2*lane];
    float2 kf = __half22float2(kh);
    float a0 = nrm*kf.x, a1 = nrm*kf.y;
    ka0 += a0; ka1 += a1;
    int base = lane & ~3;
    #pragma unroll
    for(int jj=0; jj<4; jj++){
      unsigned u = __shfl_sync(FULLMASK, vu, base + jj);
      float2 vf = __half22float2(*(__half2*)&u);
      m0[2*jj]   = fmaf(a0, vf.x, m0[2*jj]);
      m0[2*jj+1] = fmaf(a0, vf.y, m0[2*jj+1]);
      m1[2*jj]   = fmaf(a1, vf.x, m1[2*jj]);
      m1[2*jj+1] = fmaf(a1, vf.y, m1[2*jj+1]);
    }
    row = nrow; nrm = nnrm;
  }

  {
    union { uint4 u; __half2 h[4]; } p;
    p.h[0]=__floats2half2_rn(m0[0],m0[1]); p.h[1]=__floats2half2_rn(m0[2],m0[3]);
    p.h[2]=__floats2half2_rn(m0[4],m0[5]); p.h[3]=__floats2half2_rn(m0[6],m0[7]);
    *(uint4*)&g_M1h[(size_t)n*512 + lane*8] = p.u;
    p.h[0]=__floats2half2_rn(m1[0],m1[1]); p.h[1]=__floats2half2_rn(m1[2],m1[3]);
    p.h[2]=__floats2half2_rn(m1[4],m1[5]); p.h[3]=__floats2half2_rn(m1[6],m1[7]);
    *(uint4*)&g_M1h[(size_t)n*512 + 256 + lane*8] = p.u;
  }
  *(__half2*)&g_K1h[n*64 + 2*lane] = __floats2half2_rn(ka0, ka1);

  float2 qv = *(const float2*)&g_Q[n*64 + 2*lane];
  float p[8];
  #pragma unroll
  for(int j=0;j<8;j++) p[j] = qv.x*m0[j] + qv.y*m1[j];
  #pragma unroll
  for(int j=0;j<8;j++){
    p[j] += __shfl_xor_sync(FULLMASK, p[j], 1);
    p[j] += __shfl_xor_sync(FULLMASK, p[j], 2);
  }
  float c = qv.x*ka0 + qv.y*ka1;
  c += __shfl_xor_sync(FULLMASK, c, 1);
  c += __shfl_xor_sync(FULLMASK, c, 2);
  int h = lane >> 2, sub = lane & 3;
  if(sub < 2){
    bool lo = (sub == 0);
    float r0 = lo ? p[0] : p[4];
    float r1 = lo ? p[1] : p[5];
    float r2 = lo ? p[2] : p[6];
    float r3 = lo ? p[3] : p[7];
    float inv = sgam[h] / (c + CSTF);
    float hp0 = shop0;
    const float4 vv = *(const float4*)&g_V[n*64 + h*8 + sub*4];
    float4 hv;
    hv.x = fmaf(vv.x, hp0, inv*r0);
    hv.y = fmaf(vv.y, hp0, inv*r1);
    hv.z = fmaf(vv.z, hp0, inv*r2);
    hv.w = fmaf(vv.w, hp0, inv*r3);
    *(float4*)&g_hidden[n*64 + h*8 + sub*4] = hv;
  }
  if(lane == 0) g_cur[n] = 0;
}

// ---------------- hop 2 ----------------
__global__ void __launch_bounds__(256) k_pass3(const float* __restrict__ hopwise,
                                               const float* __restrict__ headwise){
  __shared__ float sgam[8];
  int tid = threadIdx.x;
  if(tid < 8){
    float mx = -1e30f;
    for(int hh=0; hh<8; hh++) mx = fmaxf(mx, headwise[hh*2+1]);
    float ss = 0.f;
    for(int hh=0; hh<8; hh++) ss += expf(headwise[hh*2+1]-mx);
    sgam[tid] = hopwise[2] * expf(headwise[tid*2+1]-mx) / ss;
  }
  __syncthreads();

  int n    = (blockIdx.x*256 + tid) >> 5;
  int lane = tid & 31;
  int beg = colp(n), end = colp(n+1);
  float m[16];
  #pragma unroll
  for(int t=0;t<16;t++) m[t] = 0.f;
  float ca = 0.f, cb = 0.f;

  int row = 0; float nrm = 0.f;
  if(beg < end){ row = g_srow[beg]; nrm = g_snorm[beg]; }
  for(int e=beg; e<end; e++){
    int nrow = 0; float nnrm = 0.f;
    if(e+1 < end){ nrow = g_srow[e+1]; nnrm = g_snorm[e+1]; }
    const __half* Mr = &g_M1h[(size_t)row*512];
    uint4 a = *(const uint4*)(Mr + lane*8);
    uint4 b = *(const uint4*)(Mr + 256 + lane*8);
    __half2 kv = *(const __half2*)&g_K1h[row*64 + 2*lane];
    float2 f;
    f = __half22float2(*(__half2*)&a.x); m[0]=fmaf(nrm,f.x,m[0]);   m[1]=fmaf(nrm,f.y,m[1]);
    f = __half22float2(*(__half2*)&a.y); m[2]=fmaf(nrm,f.x,m[2]);   m[3]=fmaf(nrm,f.y,m[3]);
    f = __half22float2(*(__half2*)&a.z); m[4]=fmaf(nrm,f.x,m[4]);   m[5]=fmaf(nrm,f.y,m[5]);
    f = __half22float2(*(__half2*)&a.w); m[6]=fmaf(nrm,f.x,m[6]);   m[7]=fmaf(nrm,f.y,m[7]);
    f = __half22float2(*(__half2*)&b.x); m[8]=fmaf(nrm,f.x,m[8]);   m[9]=fmaf(nrm,f.y,m[9]);
    f = __half22float2(*(__half2*)&b.y); m[10]=fmaf(nrm,f.x,m[10]); m[11]=fmaf(nrm,f.y,m[11]);
    f = __half22float2(*(__half2*)&b.z); m[12]=fmaf(nrm,f.x,m[12]); m[13]=fmaf(nrm,f.y,m[13]);
    f = __half22float2(*(__half2*)&b.w); m[14]=fmaf(nrm,f.x,m[14]); m[15]=fmaf(nrm,f.y,m[15]);
    float2 kf = __half22float2(kv);
    ca = fmaf(nrm, kf.x, ca);
    cb = fmaf(nrm, kf.y, cb);
    row = nrow; nrm = nnrm;
  }

  float2 qv = *(const float2*)&g_Q[n*64 + 2*lane];
  float p[8];
  #pragma unroll
  for(int j=0;j<8;j++) p[j] = qv.x*m[j] + qv.y*m[8+j];
  #pragma unroll
  for(int j=0;j<8;j++){
    p[j] += __shfl_xor_sync(FULLMASK, p[j], 1);
    p[j] += __shfl_xor_sync(FULLMASK, p[j], 2);
  }
  float c = qv.x*ca + qv.y*cb;
  c += __shfl_xor_sync(FULLMASK, c, 1);
  c += __shfl_xor_sync(FULLMASK, c, 2);
  int h = lane >> 2, sub = lane & 3;
  if(sub < 2){
    bool lo = (sub == 0);
    float r0 = lo ? p[0] : p[4];
    float r1 = lo ? p[1] : p[5];
    float r2 = lo ? p[2] : p[6];
    float r3 = lo ? p[3] : p[7];
    float inv = sgam[h] / (c + CSTF);
    float4* hp = (float4*)&g_hidden[n*64 + h*8 + sub*4];
    float4 hv = *hp;
    hv.x += inv*r0; hv.y += inv*r1; hv.z += inv*r2; hv.w += inv*r3;
    *hp = hv;
  }
}

// ---------------- launch ----------------
extern "C" void kernel_launch(void* const* d_in, const int* in_sizes, int n_in,
                              void* d_out, int out_size){
  const float* x        = (const float*)d_in[0];
  const int*   ei       = (const int*)  d_in[1];
  const float* Wq       = (const float*)d_in[3];
  const float* bq       = (const float*)d_in[4];
  const float* Wk       = (const float*)d_in[5];
  const float* bk       = (const float*)d_in[6];
  const float* Wv       = (const float*)d_in[7];
  const float* bv       = (const float*)d_in[8];
  const float* Wo       = (const float*)d_in[9];
  const float* bo       = (const float*)d_in[10];
  const float* hopwise  = (const float*)d_in[11];
  const float* headwise = (const float*)d_in[12];
  float* out = (float*)d_out;

  cudaFuncSetAttribute(k_gemmQKV_hist, cudaFuncAttributeMaxDynamicSharedMemorySize, SMEMQKV);

  k_gemmQKV_hist<<<2*GEMMB, 256, SMEMQKV>>>(ei, x, Wq, bq, Wk, bk, Wv, bv);
  k_scan1  <<<NB, 256>>>();
  k_scatter<<<NE/256, 256>>>(ei);
  k_pass1  <<<NN/8, 256>>>(hopwise, headwise);
  k_pass3  <<<NN/8, 256>>>(hopwise, headwise);
  k_gemmO  <<<(NN+63)/64, 256, SMEMO>>>(Wo, bo, out);
}

// round 7
// speedup vs baseline: 1.0194x; 1.0171x over previous
#include <cuda_runtime.h>
#include <cuda_fp16.h>

#define NN 20000
#define NE 320000
#define NB 25
#define SEG 800
#define FULLMASK 0xffffffffu
#define CSTF 1e-5f
#define CSRB 148
#define GEMMB 313

#define FMA2(acc, a, b) asm("fma.rn.f32x2 %0, %1, %2, %0;" : "+l"(acc) : "l"(a), "l"(b))
#define PACK2(xx, xv)   asm("mov.b64 %0, {%1, %1};" : "=l"(xx) : "f"(xv))

union U2 { unsigned long long u; float2 f; };

// ---------------- device scratch (static; every call restores zeros) ----------------
__device__ float  g_Q[NN*64];
__device__ __half g_Kh[NN*64];
__device__ __half g_Vh[NN*64];
__device__ float  g_V[NN*64];
__device__ float  g_hidden[NN*64];
__device__ __half g_M1h[(size_t)NN*512];
__device__ __half g_K1h[NN*64];
__device__ float  g_deginv[NN];
__device__ int    g_cnt[NN];               // zeroed inside fused scan phase
__device__ int    g_cur[NN];               // zeroed by k_pass1 tail
__device__ int    g_colptr[NN+1];
__device__ int    g_bsum[NB];
__device__ int    g_boff[NB+1];
__device__ int    g_srow[NE];
__device__ float  g_snorm[NE];
__device__ volatile int g_ph1, g_ph2, g_ph3;   // phase counters (reset in-kernel)

// int64-vs-int32 detect: sample 32 odd words; all zero => int64.
__device__ __forceinline__ void detect64(const int* __restrict__ ei, int tid, int* s64){
  if(tid < 32){
    bool z = (ei[2*(tid*9973)+1] == 0);
    unsigned bal = __ballot_sync(FULLMASK, z);
    if(tid==0) *s64 = (bal == FULLMASK) ? 1 : 0;
  }
}

__device__ __forceinline__ int colp(int i){
  return g_colptr[i] + g_boff[i/SEG];
}

// ============ fused launch: blocks [0,CSRB) build CSR (3 phases, 2 spin barriers),
// ============ blocks [CSRB, CSRB+GEMMB) run the QKV GEMM concurrently.
#define SMEMQKV (16384 + 49152 + 768)
__global__ void __launch_bounds__(256,3) k_fused(const int* __restrict__ ei,
    const float* __restrict__ x,
    const float* __restrict__ Wq, const float* __restrict__ bq,
    const float* __restrict__ Wk, const float* __restrict__ bk,
    const float* __restrict__ Wv, const float* __restrict__ bv){
  extern __shared__ __align__(16) char dsm[];
  int tid = threadIdx.x;
  int bid = blockIdx.x;

  if(bid < CSRB){
    // -------- CSR builder --------
    int* s     = (int*)dsm;                    // SEG
    int* wtot  = (int*)(dsm + SEG*4);          // 8
    int* ps64  = (int*)(dsm + SEG*4 + 32);     // 1
    int* sboff = (int*)(dsm + SEG*4 + 64);     // NB
    detect64(ei, tid, ps64);
    __syncthreads();
    int s64 = *ps64;

    // phase 1: degree histogram (grid-stride over CSRB blocks)
    for(int e = bid*256 + tid; e < NE; e += CSRB*256){
      int c = s64 ? ei[2*(NE+e)] : ei[NE+e];
      atomicAdd(&g_cnt[c], 1);
    }
    // barrier 1
    __threadfence();
    __syncthreads();
    if(tid == 0){
      atomicAdd((int*)&g_ph1, 1);
      while(g_ph1 < CSRB) {}
    }
    __syncthreads();
    __threadfence();

    // phase 2: per-segment exclusive scan + deginv (blocks 0..NB-1); zero g_cnt
    if(bid < NB){
      for(int i=tid; i<SEG; i+=256){ s[i] = __ldcg(&g_cnt[bid*SEG+i]); g_cnt[bid*SEG+i] = 0; }
      __syncthreads();
      int c0=0,c1=0,c2=0,c3=0,v=0;
      if(tid < 200){
        c0=s[4*tid]; c1=s[4*tid+1]; c2=s[4*tid+2]; c3=s[4*tid+3];
        v = c0+c1+c2+c3;
      }
      int lane = tid & 31, wid = tid >> 5;
      int xx = v;
      #pragma unroll
      for(int off=1; off<32; off<<=1){ int y=__shfl_up_sync(FULLMASK,xx,off); if(lane>=off) xx+=y; }
      if(lane==31) wtot[wid] = xx;
      __syncthreads();
      if(tid < 32){
        int w = (tid < 7) ? wtot[tid] : 0;
        #pragma unroll
        for(int off=1; off<32; off<<=1){ int y=__shfl_up_sync(FULLMASK,w,off); if(tid>=off) w+=y; }
        if(tid < 7) wtot[tid] = w;
        if(tid == 6) g_bsum[bid] = w;
      }
      __syncthreads();
      if(tid < 200){
        int pre = xx - v + (wid>0 ? wtot[wid-1] : 0);
        int base = bid*SEG + 4*tid;
        g_colptr[base+0] = pre;
        g_colptr[base+1] = pre + c0;
        g_colptr[base+2] = pre + c0 + c1;
        g_colptr[base+3] = pre + c0 + c1 + c2;
        g_deginv[base+0] = c0 ? rsqrtf((float)c0) : 0.f;
        g_deginv[base+1] = c1 ? rsqrtf((float)c1) : 0.f;
        g_deginv[base+2] = c2 ? rsqrtf((float)c2) : 0.f;
        g_deginv[base+3] = c3 ? rsqrtf((float)c3) : 0.f;
      }
    }
    // barrier 2
    __threadfence();
    __syncthreads();
    if(tid == 0){
      atomicAdd((int*)&g_ph2, 1);
      while(g_ph2 < CSRB) {}
      if(bid == 0) g_ph1 = 0;     // safe: everyone has passed barrier 1
    }
    __syncthreads();
    __threadfence();

    // phase 3: block offsets + scatter
    if(tid < 32){
      int v = (tid < NB) ? __ldcg(&g_bsum[tid]) : 0;
      int xx = v;
      #pragma unroll
      for(int off=1; off<32; off<<=1){ int y=__shfl_up_sync(FULLMASK,xx,off); if(tid>=off) xx+=y; }
      if(tid < NB) sboff[tid] = xx - v;
      if(bid == 0){
        if(tid < NB) g_boff[tid] = xx - v;
        if(tid == 31) g_boff[NB] = NE;
      }
    }
    __syncthreads();
    for(int e = bid*256 + tid; e < NE; e += CSRB*256){
      int r = s64 ? ei[2*e]      : ei[e];
      int c = s64 ? ei[2*(NE+e)] : ei[NE+e];
      int pos = __ldcg(&g_colptr[c]) + sboff[c/SEG] + atomicAdd(&g_cur[c], 1);
      g_srow[pos]  = r;
      g_snorm[pos] = __ldcg(&g_deginv[r]) * __ldcg(&g_deginv[c]);
    }
    // final: reset remaining phase counters (block 0 waits for all)
    __threadfence();
    __syncthreads();
    if(tid == 0){
      atomicAdd((int*)&g_ph3, 1);
      if(bid == 0){
        while(g_ph3 < CSRB) {}
        g_ph2 = 0; g_ph3 = 0;
      }
    }
    return;
  }

  // -------- QKV GEMM part --------
  float*  xsf = (float*)dsm;                        // [n*64 + i]
  float2* ws2 = (float2*)(dsm + 16384);             // [m*2048 + i*32 + op]
  float2* bs2 = (float2*)(dsm + 16384 + 49152);     // [m*32 + op]
  int nb = (bid - CSRB)*64;
  for(int idx = tid; idx < 4096; idx += 256){
    int n = idx >> 6, i = idx & 63;
    xsf[idx] = (nb+n < NN) ? x[(nb+n)*64 + i] : 0.f;
    int wi = idx >> 6, wo = idx & 63;
    int wop = wo & 31, hi = wo >> 5;
    ((float*)&ws2[0*2048 + wi*32 + wop])[hi] = Wq[idx];
    ((float*)&ws2[1*2048 + wi*32 + wop])[hi] = Wk[idx];
    ((float*)&ws2[2*2048 + wi*32 + wop])[hi] = Wv[idx];
  }
  if(tid < 32){
    bs2[tid]    = make_float2(bq[tid], bq[tid+32]);
    bs2[32+tid] = make_float2(bk[tid], bk[tid+32]);
    bs2[64+tid] = make_float2(bv[tid], bv[tid+32]);
  }
  __syncthreads();

  int op = tid & 31;
  int ng = (tid >> 5) << 3;
  U2 acc[3][8];
  #pragma unroll
  for(int m=0;m<3;m++){
    U2 b0; b0.f = bs2[m*32+op];
    #pragma unroll
    for(int g=0;g<8;g++) acc[m][g] = b0;
  }
  const unsigned long long* wsu = (const unsigned long long*)ws2;
  #pragma unroll 4
  for(int i=0; i<64; i++){
    unsigned long long w0 = wsu[0*2048 + i*32 + op];
    unsigned long long w1 = wsu[1*2048 + i*32 + op];
    unsigned long long w2 = wsu[2*2048 + i*32 + op];
    #pragma unroll
    for(int g=0;g<8;g++){
      float xv = xsf[(ng+g)*64 + i];
      unsigned long long xx; PACK2(xx, xv);
      FMA2(acc[0][g].u, xx, w0);
      FMA2(acc[1][g].u, xx, w1);
      FMA2(acc[2][g].u, xx, w2);
    }
  }
  #pragma unroll
  for(int g=0;g<8;g++){
    int n = nb + ng + g;
    if(n < NN){
      float q0 = acc[0][g].f.x, q1 = acc[0][g].f.y;
      q0 = (q0 > 0.f) ? (q0 + 1.f) : __expf(q0);
      q1 = (q1 > 0.f) ? (q1 + 1.f) : __expf(q1);
      g_Q[n*64+op] = q0; g_Q[n*64+op+32] = q1;
      float k0 = acc[1][g].f.x, k1 = acc[1][g].f.y;
      k0 = (k0 > 0.f) ? (k0 + 1.f) : __expf(k0);
      k1 = (k1 > 0.f) ? (k1 + 1.f) : __expf(k1);
      g_Kh[n*64+op] = __float2half_rn(k0); g_Kh[n*64+op+32] = __float2half_rn(k1);
      float v0 = acc[2][g].f.x, v1 = acc[2][g].f.y;
      g_V[n*64+op] = v0; g_V[n*64+op+32] = v1;
      g_Vh[n*64+op] = __float2half_rn(v0); g_Vh[n*64+op+32] = __float2half_rn(v1);
    }
  }
}

// ---------------- output GEMM: hidden @ Wo + bo -> dout ----------------
#define SMEMO (16384 + 16384 + 256)
__global__ void __launch_bounds__(256,4) k_gemmO(const float* __restrict__ Wo,
                                                 const float* __restrict__ bo,
                                                 float* __restrict__ dout){
  extern __shared__ __align__(16) char dsm[];
  float*  xsf = (float*)dsm;
  float2* ws2 = (float2*)(dsm + 16384);
  float2* bs2 = (float2*)(dsm + 16384 + 16384);
  int nb = blockIdx.x*64;
  int tid = threadIdx.x;
  for(int idx = tid; idx < 4096; idx += 256){
    int n = idx >> 6;
    xsf[idx] = (nb+n < NN) ? g_hidden[nb*64 + idx] : 0.f;
    int wi = idx >> 6, wo = idx & 63;
    ((float*)&ws2[wi*32 + (wo & 31)])[wo >> 5] = Wo[idx];
  }
  if(tid < 32) bs2[tid] = make_float2(bo[tid], bo[tid+32]);
  __syncthreads();

  int op = tid & 31;
  int ng = (tid >> 5) << 3;
  U2 acc[8];
  { U2 b0; b0.f = bs2[op];
    #pragma unroll
    for(int g=0;g<8;g++) acc[g] = b0; }
  const unsigned long long* wsu = (const unsigned long long*)ws2;
  #pragma unroll 4
  for(int i=0; i<64; i++){
    unsigned long long w0 = wsu[i*32 + op];
    #pragma unroll
    for(int g=0;g<8;g++){
      float xv = xsf[(ng+g)*64 + i];
      unsigned long long xx; PACK2(xx, xv);
      FMA2(acc[g].u, xx, w0);
    }
  }
  #pragma unroll
  for(int g=0;g<8;g++){
    int n = nb + ng + g;
    if(n < NN){
      dout[n*64+op]    = acc[g].f.x;
      dout[n*64+op+32] = acc[g].f.y;
    }
  }
}

// ---------------- hop 1: no shuffles (direct V LDG.128 per head), f32x2 accum -----------
__global__ void __launch_bounds__(256) k_pass1(const float* __restrict__ hopwise,
                                               const float* __restrict__ headwise){
  __shared__ float sgam[8];
  __shared__ float shop0;
  int tid = threadIdx.x;
  if(tid < 8){
    float mx = -1e30f;
    for(int hh=0; hh<8; hh++) mx = fmaxf(mx, headwise[hh*2]);
    float ss = 0.f;
    for(int hh=0; hh<8; hh++) ss += expf(headwise[hh*2]-mx);
    sgam[tid] = hopwise[1] * expf(headwise[tid*2]-mx) / ss;
  }
  if(tid == 8) shop0 = hopwise[0];
  __syncthreads();

  int n    = (blockIdx.x*256 + tid) >> 5;
  int lane = tid & 31;
  int h8   = (lane >> 2) << 3;          // head base in 64-dim
  int beg = colp(n), end = colp(n+1);
  U2 m0p[4], m1p[4];
  #pragma unroll
  for(int j=0;j<4;j++){ m0p[j].f = make_float2(0.f,0.f); m1p[j].f = make_float2(0.f,0.f); }
  float ka0 = 0.f, ka1 = 0.f;

  int row = 0; float nrm = 0.f;
  if(beg < end){ row = g_srow[beg]; nrm = g_snorm[beg]; }
  for(int e=beg; e<end; e++){
    int nrow = 0; float nnrm = 0.f;
    if(e+1 < end){ nrow = g_srow[e+1]; nnrm = g_snorm[e+1]; }
    __half2 kh = *(const __half2*)&g_Kh[row*64 + 2*lane];
    uint4   vv = *(const uint4*)  &g_Vh[row*64 + h8];      // 8 halves of this head
    float2 kf = __half22float2(kh);
    float a0 = nrm*kf.x, a1 = nrm*kf.y;
    ka0 += a0; ka1 += a1;
    unsigned long long A0, A1; PACK2(A0, a0); PACK2(A1, a1);
    U2 v01, v23, v45, v67;
    v01.f = __half22float2(*(__half2*)&vv.x);
    v23.f = __half22float2(*(__half2*)&vv.y);
    v45.f = __half22float2(*(__half2*)&vv.z);
    v67.f = __half22float2(*(__half2*)&vv.w);
    FMA2(m0p[0].u, A0, v01.u); FMA2(m0p[1].u, A0, v23.u);
    FMA2(m0p[2].u, A0, v45.u); FMA2(m0p[3].u, A0, v67.u);
    FMA2(m1p[0].u, A1, v01.u); FMA2(m1p[1].u, A1, v23.u);
    FMA2(m1p[2].u, A1, v45.u); FMA2(m1p[3].u, A1, v67.u);
    row = nrow; nrm = nnrm;
  }

  float m0[8], m1[8];
  #pragma unroll
  for(int j=0;j<4;j++){
    m0[2*j] = m0p[j].f.x; m0[2*j+1] = m0p[j].f.y;
    m1[2*j] = m1p[j].f.x; m1[2*j+1] = m1p[j].f.y;
  }
  {
    union { uint4 u; __half2 h[4]; } p;
    p.h[0]=__floats2half2_rn(m0[0],m0[1]); p.h[1]=__floats2half2_rn(m0[2],m0[3]);
    p.h[2]=__floats2half2_rn(m0[4],m0[5]); p.h[3]=__floats2half2_rn(m0[6],m0[7]);
    *(uint4*)&g_M1h[(size_t)n*512 + lane*8] = p.u;
    p.h[0]=__floats2half2_rn(m1[0],m1[1]); p.h[1]=__floats2half2_rn(m1[2],m1[3]);
    p.h[2]=__floats2half2_rn(m1[4],m1[5]); p.h[3]=__floats2half2_rn(m1[6],m1[7]);
    *(uint4*)&g_M1h[(size_t)n*512 + 256 + lane*8] = p.u;
  }
  *(__half2*)&g_K1h[n*64 + 2*lane] = __floats2half2_rn(ka0, ka1);

  float2 qv = *(const float2*)&g_Q[n*64 + 2*lane];
  float p[8];
  #pragma unroll
  for(int j=0;j<8;j++) p[j] = qv.x*m0[j] + qv.y*m1[j];
  #pragma unroll
  for(int j=0;j<8;j++){
    p[j] += __shfl_xor_sync(FULLMASK, p[j], 1);
    p[j] += __shfl_xor_sync(FULLMASK, p[j], 2);
  }
  float c = qv.x*ka0 + qv.y*ka1;
  c += __shfl_xor_sync(FULLMASK, c, 1);
  c += __shfl_xor_sync(FULLMASK, c, 2);
  int h = lane >> 2, sub = lane & 3;
  if(sub < 2){
    bool lo = (sub == 0);
    float r0 = lo ? p[0] : p[4];
    float r1 = lo ? p[1] : p[5];
    float r2 = lo ? p[2] : p[6];
    float r3 = lo ? p[3] : p[7];
    float inv = sgam[h] / (c + CSTF);
    float hp0 = shop0;
    const float4 vv = *(const float4*)&g_V[n*64 + h*8 + sub*4];
    float4 hv;
    hv.x = fmaf(vv.x, hp0, inv*r0);
    hv.y = fmaf(vv.y, hp0, inv*r1);
    hv.z = fmaf(vv.z, hp0, inv*r2);
    hv.w = fmaf(vv.w, hp0, inv*r3);
    *(float4*)&g_hidden[n*64 + h*8 + sub*4] = hv;
  }
  if(lane == 0) g_cur[n] = 0;
}

// ---------------- hop 2: f32x2 accumulation ----------------
__global__ void __launch_bounds__(256) k_pass3(const float* __restrict__ hopwise,
                                               const float* __restrict__ headwise){
  __shared__ float sgam[8];
  int tid = threadIdx.x;
  if(tid < 8){
    float mx = -1e30f;
    for(int hh=0; hh<8; hh++) mx = fmaxf(mx, headwise[hh*2+1]);
    float ss = 0.f;
    for(int hh=0; hh<8; hh++) ss += expf(headwise[hh*2+1]-mx);
    sgam[tid] = hopwise[2] * expf(headwise[tid*2+1]-mx) / ss;
  }
  __syncthreads();

  int n    = (blockIdx.x*256 + tid) >> 5;
  int lane = tid & 31;
  int beg = colp(n), end = colp(n+1);
  U2 ma[4], mb[4], kap;
  #pragma unroll
  for(int j=0;j<4;j++){ ma[j].f = make_float2(0.f,0.f); mb[j].f = make_float2(0.f,0.f); }
  kap.f = make_float2(0.f,0.f);

  int row = 0; float nrm = 0.f;
  if(beg < end){ row = g_srow[beg]; nrm = g_snorm[beg]; }
  for(int e=beg; e<end; e++){
    int nrow = 0; float nnrm = 0.f;
    if(e+1 < end){ nrow = g_srow[e+1]; nnrm = g_snorm[e+1]; }
    const __half* Mr = &g_M1h[(size_t)row*512];
    uint4 a = *(const uint4*)(Mr + lane*8);
    uint4 b = *(const uint4*)(Mr + 256 + lane*8);
    __half2 kv = *(const __half2*)&g_K1h[row*64 + 2*lane];
    unsigned long long N2; PACK2(N2, nrm);
    U2 t;
    t.f = __half22float2(*(__half2*)&a.x); FMA2(ma[0].u, N2, t.u);
    t.f = __half22float2(*(__half2*)&a.y); FMA2(ma[1].u, N2, t.u);
    t.f = __half22float2(*(__half2*)&a.z); FMA2(ma[2].u, N2, t.u);
    t.f = __half22float2(*(__half2*)&a.w); FMA2(ma[3].u, N2, t.u);
    t.f = __half22float2(*(__half2*)&b.x); FMA2(mb[0].u, N2, t.u);
    t.f = __half22float2(*(__half2*)&b.y); FMA2(mb[1].u, N2, t.u);
    t.f = __half22float2(*(__half2*)&b.z); FMA2(mb[2].u, N2, t.u);
    t.f = __half22float2(*(__half2*)&b.w); FMA2(mb[3].u, N2, t.u);
    t.f = __half22float2(kv);              FMA2(kap.u,  N2, t.u);
    row = nrow; nrm = nnrm;
  }

  float2 qv = *(const float2*)&g_Q[n*64 + 2*lane];
  float p[8];
  #pragma unroll
  for(int j=0;j<4;j++){
    p[2*j]   = qv.x*ma[j].f.x + qv.y*mb[j].f.x;
    p[2*j+1] = qv.x*ma[j].f.y + qv.y*mb[j].f.y;
  }
  #pragma unroll
  for(int j=0;j<8;j++){
    p[j] += __shfl_xor_sync(FULLMASK, p[j], 1);
    p[j] += __shfl_xor_sync(FULLMASK, p[j], 2);
  }
  float c = qv.x*kap.f.x + qv.y*kap.f.y;
  c += __shfl_xor_sync(FULLMASK, c, 1);
  c += __shfl_xor_sync(FULLMASK, c, 2);
  int h = lane >> 2, sub = lane & 3;
  if(sub < 2){
    bool lo = (sub == 0);
    float r0 = lo ? p[0] : p[4];
    float r1 = lo ? p[1] : p[5];
    float r2 = lo ? p[2] : p[6];
    float r3 = lo ? p[3] : p[7];
    float inv = sgam[h] / (c + CSTF);
    float4* hp = (float4*)&g_hidden[n*64 + h*8 + sub*4];
    float4 hv = *hp;
    hv.x += inv*r0; hv.y += inv*r1; hv.z += inv*r2; hv.w += inv*r3;
    *hp = hv;
  }
}

// ---------------- launch ----------------
extern "C" void kernel_launch(void* const* d_in, const int* in_sizes, int n_in,
                              void* d_out, int out_size){
  const float* x        = (const float*)d_in[0];
  const int*   ei       = (const int*)  d_in[1];
  const float* Wq       = (const float*)d_in[3];
  const float* bq       = (const float*)d_in[4];
  const float* Wk       = (const float*)d_in[5];
  const float* bk       = (const float*)d_in[6];
  const float* Wv       = (const float*)d_in[7];
  const float* bv       = (const float*)d_in[8];
  const float* Wo       = (const float*)d_in[9];
  const float* bo       = (const float*)d_in[10];
  const float* hopwise  = (const float*)d_in[11];
  const float* headwise = (const float*)d_in[12];
  float* out = (float*)d_out;

  cudaFuncSetAttribute(k_fused, cudaFuncAttributeMaxDynamicSharedMemorySize, SMEMQKV);

  k_fused <<<CSRB + GEMMB, 256, SMEMQKV>>>(ei, x, Wq, bq, Wk, bk, Wv, bv);
  k_pass1 <<<NN/8, 256>>>(hopwise, headwise);
  k_pass3 <<<NN/8, 256>>>(hopwise, headwise);
  k_gemmO <<<(NN+63)/64, 256, SMEMO>>>(Wo, bo, out);
}